// round 16
// baseline (speedup 1.0000x reference)
#include <cuda_runtime.h>
#include <cuda_fp16.h>
#include <cstdint>

// Problem constants (fixed by the reference setup)
#define HH 240
#define WW 304
#define IN_CH 16
#define OUT_CH 32
#define CIN 18            // pos + neg + 16 features
#define CPAD 20           // dense per-pixel stride: [pos,neg,f0..f15,-,-]
#define BB 8
#define NPIX (BB * HH * WW)          // 583680
#define NMAX (BB * 65536)            // 524288 events
#define WSIZE (3 * 3 * CIN * OUT_CH) // 5184 weights

// Conv tiling (fp16 tensor cores, legacy mma path)
#define TLX 32            // output tile width
#define TLY 16            // output tile height
#define HLX (TLX + 2)     // 34 staged cols
#define HLY (TLY + 2)     // 18 staged rows
#define STPX (HLX * HLY)  // 612 staged pixels
#define APITCH 40         // halves per staged pixel (32 data + 8 pad = 80B row)
#define BTAP 768          // halves per tap of B ldmatrix tiles (12 x 8x8)
#define CONV_THREADS 1024

// Dynamic smem layout (bytes)
#define SA_BYTES (STPX * APITCH * 2)        // 48960
#define SB_BYTES (9 * BTAP * 2)             // 13824
#define SC_BYTES (STPX * 4)                 //  2448
#define DYN_BYTES (SA_BYTES + SB_BYTES + SC_BYTES)  // 65232

// Scratch (device globals: no allocation allowed in kernel_launch)
__device__ float g_dense[(size_t)NPIX * CPAD];   // ~46.7 MB accumulator
__device__ float g_conv [(size_t)NPIX * OUT_CH]; // ~74.7 MB conv output
__device__ int   g_key  [NMAX];

__device__ __forceinline__ uint32_t smem_u32(const void* p) {
    uint32_t a;
    asm("{ .reg .u64 t; cvta.to.shared.u64 t, %1; cvt.u32.u64 %0, t; }"
        : "=r"(a) : "l"(p));
    return a;
}

// ---------------------------------------------------------------------------
// 0) Zero the accumulator (must happen every graph replay)
// ---------------------------------------------------------------------------
__global__ void zero_dense_kernel() {
    const size_t n4 = (size_t)NPIX * CPAD / 4;
    size_t i = (size_t)blockIdx.x * blockDim.x + threadIdx.x;
    float4* p = reinterpret_cast<float4*>(g_dense);
    if (i < n4) p[i] = make_float4(0.f, 0.f, 0.f, 0.f);
}

// ---------------------------------------------------------------------------
// 1) Scatter: per-event vector atomics into the dense grid; cache key.
//    No explicit count channel: cnt == sum(pos) + sum(neg) (pos+neg = 1
//    exactly per event), recovered in the conv staging.
//    offsets may be int32 or int64 (values positive < 2^31, so for
//    little-endian int64 the second 32-bit word is 0).
// ---------------------------------------------------------------------------
__global__ void scatter_kernel(const float* __restrict__ events,
                               const float* __restrict__ features,
                               const int* __restrict__ offsets_raw,
                               int n, int nb) {
    int i = blockIdx.x * blockDim.x + threadIdx.x;
    if (i >= n) return;

    bool is64 = (nb > 1) ? (__ldg(&offsets_raw[1]) == 0) : false;

    float4 ev = *reinterpret_cast<const float4*>(events + (size_t)i * 4);

    int b = 0;
    #pragma unroll
    for (int j = 0; j < BB; j++) {
        if (j < nb) {
            long long oj = is64
                ? __ldg(reinterpret_cast<const long long*>(offsets_raw) + j)
                : (long long)__ldg(&offsets_raw[j]);
            if (oj <= (long long)i) b++;
        }
    }

    int yi = __float2int_rn(ev.y * (float)HH);
    int xi = __float2int_rn(ev.x * (float)WW);
    yi = min(max(yi, 0), HH - 1);
    xi = min(max(xi, 0), WW - 1);
    int key = (b * HH + yi) * WW + xi;
    g_key[i] = key;

    float pos = ev.w;
    float neg = 1.0f - pos;

    const float4* f = reinterpret_cast<const float4*>(features + (size_t)i * IN_CH);
    float4 f0 = f[0], f1 = f[1], f2 = f[2], f3 = f[3];

    float* d = g_dense + (size_t)key * CPAD;
    atomicAdd(reinterpret_cast<float4*>(d +  0), make_float4(pos,  neg,  f0.x, f0.y));
    atomicAdd(reinterpret_cast<float4*>(d +  4), make_float4(f0.z, f0.w, f1.x, f1.y));
    atomicAdd(reinterpret_cast<float4*>(d +  8), make_float4(f1.z, f1.w, f2.x, f2.y));
    atomicAdd(reinterpret_cast<float4*>(d + 12), make_float4(f2.z, f2.w, f3.x, f3.y));
    atomicAdd(reinterpret_cast<float2*>(d + 16), make_float2(f3.z, f3.w));
}

// ---------------------------------------------------------------------------
// 2) Conv 3x3 SAME via fp16 mma (fp32 accum), all fragments via ldmatrix.
//    Block: 1024 thr = 32 warps; output tile 32x16 px; warp: 16 px x 32 oc.
//    Per tap: 1x m16n8k16 + 1x m16n8k8 per n-tile (18 ch -> 16 + 2).
//    A: halo 34x18 px, pitch 80B (conflict-free ldmatrix). B: 8x8 ldmatrix
//    tiles, 3x ldmatrix.x4 per tap. Epilogue skips stores for empty pixels.
// ---------------------------------------------------------------------------
extern __shared__ char dynsmem[];

__global__ __launch_bounds__(CONV_THREADS) void conv_hmma_kernel(const float* __restrict__ weight) {
    __half* sA   = reinterpret_cast<__half*>(dynsmem);
    __half* sB   = reinterpret_cast<__half*>(dynsmem + SA_BYTES);
    float*  sCnt = reinterpret_cast<float*>(dynsmem + SA_BYTES + SB_BYTES);

    const int tid = threadIdx.x;
    const int b  = blockIdx.z;
    const int y0 = blockIdx.y * TLY;
    const int x0 = blockIdx.x * TLX;

    // ---- stage B as ldmatrix tiles ----
    // m 0..7: nt = m>>1, kg = m&1 ; m 8..11: nt = m-8, kg = 2
    // element e: n_local = e>>3, kk = e&7 ; value = W[tap][kg*8+kk][nt*8+n_local]
    for (int i = tid; i < 9 * BTAP; i += CONV_THREADS) {
        int tap = i / BTAP;
        int r   = i - tap * BTAP;
        int m   = r >> 6;
        int e   = r & 63;
        int nl  = e >> 3;
        int kk  = e & 7;
        int nt, kg;
        if (m < 8) { nt = m >> 1; kg = m & 1; } else { nt = m - 8; kg = 2; }
        int nn = nt * 8 + nl;
        int k  = kg * 8 + kk;
        float v = (k < CIN) ? __ldg(&weight[(tap * CIN + k) * OUT_CH + nn]) : 0.f;
        sB[i] = __float2half_rn(v);
    }

    // ---- stage A: normalized dense pixels as fp16, zeros outside image ----
    for (int s = tid; s < STPX; s += CONV_THREADS) {
        int hy = s / HLX;
        int hx = s - hy * HLX;
        int gy = y0 + hy - 1;
        int gx = x0 + hx - 1;
        float v[CIN];
        #pragma unroll
        for (int c = 0; c < CIN; c++) v[c] = 0.f;
        float cnt = 0.f;
        if ((unsigned)gy < (unsigned)HH && (unsigned)gx < (unsigned)WW) {
            const float* d = g_dense + ((size_t)(b * HH + gy) * WW + gx) * CPAD;
            float4 a0 = *reinterpret_cast<const float4*>(d + 0);
            float4 a1 = *reinterpret_cast<const float4*>(d + 4);
            float4 a2 = *reinterpret_cast<const float4*>(d + 8);
            float4 a3 = *reinterpret_cast<const float4*>(d + 12);
            float2 a4 = *reinterpret_cast<const float2*>(d + 16); // f14,f15
            cnt = a0.x + a0.y;   // sum(pos) + sum(neg) == event count (exact)
            float inv = 1.0f / fmaxf(cnt, 1.0f);
            v[0]=a0.x*inv;  v[1]=a0.y*inv;  v[2]=a0.z*inv;  v[3]=a0.w*inv;
            v[4]=a1.x*inv;  v[5]=a1.y*inv;  v[6]=a1.z*inv;  v[7]=a1.w*inv;
            v[8]=a2.x*inv;  v[9]=a2.y*inv;  v[10]=a2.z*inv; v[11]=a2.w*inv;
            v[12]=a3.x*inv; v[13]=a3.y*inv; v[14]=a3.z*inv; v[15]=a3.w*inv;
            v[16]=a4.x*inv; v[17]=a4.y*inv;
        }
        sCnt[s] = cnt;
        // pack 40 halves (32 data + 8 pad) = 5 x uint4
        uint32_t w[20];
        #pragma unroll
        for (int j = 0; j < 9; j++) {
            __half2 h = __floats2half2_rn(v[2*j], v[2*j+1]);
            w[j] = *reinterpret_cast<uint32_t*>(&h);
        }
        #pragma unroll
        for (int j = 9; j < 20; j++) w[j] = 0u;
        uint4* dst = reinterpret_cast<uint4*>(sA + (size_t)s * APITCH);
        #pragma unroll
        for (int q = 0; q < 5; q++)
            dst[q] = make_uint4(w[q*4+0], w[q*4+1], w[q*4+2], w[q*4+3]);
    }
    __syncthreads();

    // ---- main loop ----
    const int warp = tid >> 5;
    const int lane = tid & 31;
    const int ty   = warp >> 1;          // 0..15
    const int tx   = (warp & 1) * 16;    // 0 or 16

    const uint32_t sA_addr = smem_u32(sA);
    const uint32_t sB_addr = smem_u32(sB);
    // A x4 (k0-15): lane -> row (lane&15), half (lane>>4)
    const uint32_t lmA_off  = (uint32_t)(lane & 15) * (APITCH * 2)
                            + (uint32_t)(lane >> 4) * 16;
    // A x2 (k16-23): lanes 0-15 -> rows 0-15, +32B k-offset
    const uint32_t lmA2_off = (uint32_t)(lane & 15) * (APITCH * 2) + 32u;
    // B x4: lane -> tile (lane>>3), row (lane&7), rows are 16B apart
    const uint32_t lmB_off  = (uint32_t)(lane >> 3) * 128u
                            + (uint32_t)(lane & 7) * 16u;

    float acc[4][4];
    #pragma unroll
    for (int nt = 0; nt < 4; nt++)
        #pragma unroll
        for (int r = 0; r < 4; r++) acc[nt][r] = 0.f;

    #pragma unroll
    for (int tap = 0; tap < 9; tap++) {
        const int ky = tap / 3;
        const int kx = tap - ky * 3;
        const uint32_t px0 = (uint32_t)((ty + ky) * HLX + tx + kx);
        const uint32_t apx = sA_addr + px0 * (APITCH * 2);

        // A fragments
        uint32_t a0, a1, a2, a3, e0, e1;
        asm volatile(
            "ldmatrix.sync.aligned.m8n8.x4.shared.b16 {%0,%1,%2,%3}, [%4];"
            : "=r"(a0), "=r"(a1), "=r"(a2), "=r"(a3)
            : "r"(apx + lmA_off));
        asm volatile(
            "ldmatrix.sync.aligned.m8n8.x2.shared.b16 {%0,%1}, [%2];"
            : "=r"(e0), "=r"(e1)
            : "r"(apx + lmA2_off));

        // B fragments: 3 x4 groups
        const uint32_t bbase = sB_addr + (uint32_t)tap * (BTAP * 2) + lmB_off;
        uint32_t b00, b01, b10, b11;
        uint32_t b20, b21, b30, b31;
        uint32_t c0, c1, c2, c3;
        asm volatile(
            "ldmatrix.sync.aligned.m8n8.x4.shared.b16 {%0,%1,%2,%3}, [%4];"
            : "=r"(b00), "=r"(b01), "=r"(b10), "=r"(b11) : "r"(bbase));
        asm volatile(
            "ldmatrix.sync.aligned.m8n8.x4.shared.b16 {%0,%1,%2,%3}, [%4];"
            : "=r"(b20), "=r"(b21), "=r"(b30), "=r"(b31) : "r"(bbase + 512u));
        asm volatile(
            "ldmatrix.sync.aligned.m8n8.x4.shared.b16 {%0,%1,%2,%3}, [%4];"
            : "=r"(c0), "=r"(c1), "=r"(c2), "=r"(c3) : "r"(bbase + 1024u));

        #define MMA16(NT, B0, B1)                                             \
            asm volatile(                                                      \
                "mma.sync.aligned.m16n8k16.row.col.f32.f16.f16.f32 "           \
                "{%0,%1,%2,%3}, {%4,%5,%6,%7}, {%8,%9}, {%0,%1,%2,%3};"        \
                : "+f"(acc[NT][0]), "+f"(acc[NT][1]),                          \
                  "+f"(acc[NT][2]), "+f"(acc[NT][3])                           \
                : "r"(a0), "r"(a1), "r"(a2), "r"(a3), "r"(B0), "r"(B1))
        #define MMA8(NT, B0)                                                   \
            asm volatile(                                                      \
                "mma.sync.aligned.m16n8k8.row.col.f32.f16.f16.f32 "            \
                "{%0,%1,%2,%3}, {%4,%5}, {%6}, {%0,%1,%2,%3};"                 \
                : "+f"(acc[NT][0]), "+f"(acc[NT][1]),                          \
                  "+f"(acc[NT][2]), "+f"(acc[NT][3])                           \
                : "r"(e0), "r"(e1), "r"(B0))

        MMA16(0, b00, b01); MMA16(1, b10, b11);
        MMA16(2, b20, b21); MMA16(3, b30, b31);
        MMA8(0, c0); MMA8(1, c1); MMA8(2, c2); MMA8(3, c3);
        #undef MMA16
        #undef MMA8
    }

    // ---- epilogue: D rows = pixels (g, g+8), cols = out channels.
    //      Skip stores for pixels with no events (never gathered). ----
    const int g    = lane >> 2;   // 0..7
    const int t4   = lane & 3;    // 0..3
    const int gy   = y0 + ty;
    const int gx1  = x0 + tx + g;
    const int gx2  = gx1 + 8;
    const int sp1  = (ty + 1) * HLX + (tx + g + 1);
    const bool w1  = (gx1 < WW) && (sCnt[sp1] > 0.f);
    const bool w2  = (gx2 < WW) && (sCnt[sp1 + 8] > 0.f);
    #pragma unroll
    for (int nt = 0; nt < 4; nt++) {
        int col = nt * 8 + t4 * 2;
        if (w1)
            *reinterpret_cast<float2*>(
                g_conv + ((size_t)(b * HH + gy) * WW + gx1) * OUT_CH + col) =
                make_float2(acc[nt][0], acc[nt][1]);
        if (w2)
            *reinterpret_cast<float2*>(
                g_conv + ((size_t)(b * HH + gy) * WW + gx2) * OUT_CH + col) =
                make_float2(acc[nt][2], acc[nt][3]);
    }
}

// ---------------------------------------------------------------------------
// 3) Gather: f[i] = conv[key[i]] + bias
//    Each thread handles one quad-pair for TWO consecutive events (MLP=4).
// ---------------------------------------------------------------------------
__global__ void gather_kernel(const float* __restrict__ bias,
                              float* __restrict__ out, int n) {
    int t = blockIdx.x * blockDim.x + threadIdx.x;
    int e0 = (t >> 2) * 2;
    if (e0 >= n) return;
    int q  = (t & 3) * 2;          // quad pair: {0,1},{2,3},{4,5},{6,7}
    int2 keys = *reinterpret_cast<const int2*>(g_key + e0);

    const float4* s0 = reinterpret_cast<const float4*>(g_conv + (size_t)keys.x * OUT_CH);
    const float4* s1 = reinterpret_cast<const float4*>(g_conv + (size_t)keys.y * OUT_CH);
    float4 v00 = __ldg(s0 + q);
    float4 v01 = __ldg(s0 + q + 1);
    float4 v10 = __ldg(s1 + q);
    float4 v11 = __ldg(s1 + q + 1);
    float4 b0 = __ldg(reinterpret_cast<const float4*>(bias) + q);
    float4 b1 = __ldg(reinterpret_cast<const float4*>(bias) + q + 1);

    v00.x += b0.x; v00.y += b0.y; v00.z += b0.z; v00.w += b0.w;
    v01.x += b1.x; v01.y += b1.y; v01.z += b1.z; v01.w += b1.w;
    v10.x += b0.x; v10.y += b0.y; v10.z += b0.z; v10.w += b0.w;
    v11.x += b1.x; v11.y += b1.y; v11.z += b1.z; v11.w += b1.w;

    float4* d0 = reinterpret_cast<float4*>(out + (size_t)e0 * OUT_CH);
    d0[q]     = v00;
    d0[q + 1] = v01;
    if (e0 + 1 < n) {
        float4* d1 = reinterpret_cast<float4*>(out + (size_t)(e0 + 1) * OUT_CH);
        d1[q]     = v10;
        d1[q + 1] = v11;
    }
}

// ---------------------------------------------------------------------------
extern "C" void kernel_launch(void* const* d_in, const int* in_sizes, int n_in,
                              void* d_out, int out_size) {
    // Identify inputs by element count (robust to ordering):
    //   events: N*4, features: N*16, weight: 5184, bias: 32, offsets: 8
    const float* events   = nullptr;
    const float* features = nullptr;
    const float* weight   = nullptr;
    const float* bias     = nullptr;
    const int*   offsets  = nullptr;
    int n = 0, nb = 0;

    int big0 = -1, big1 = -1;
    for (int i = 0; i < n_in; i++) {
        int s = in_sizes[i];
        if (s == WSIZE)            weight  = (const float*)d_in[i];
        else if (s == OUT_CH)      bias    = (const float*)d_in[i];
        else if (s <= 64)        { offsets = (const int*)d_in[i]; nb = s; }
        else if (big0 < 0)         big0 = i;
        else                       big1 = i;
    }
    if (in_sizes[big0] > in_sizes[big1]) { int t = big0; big0 = big1; big1 = t; }
    events   = (const float*)d_in[big0];
    features = (const float*)d_in[big1];
    n = in_sizes[big0] / 4;
    if (nb > BB) nb = BB;

    const int T = 256;

    // opt-in smem for the conv kernel (idempotent host-side config)
    cudaFuncSetAttribute(conv_hmma_kernel,
                         cudaFuncAttributeMaxDynamicSharedMemorySize, DYN_BYTES);

    // 0) zero accumulator
    {
        size_t n4 = (size_t)NPIX * CPAD / 4;
        int blocks = (int)((n4 + T - 1) / T);
        zero_dense_kernel<<<blocks, T>>>();
    }
    // 1) scatter
    scatter_kernel<<<(n + T - 1) / T, T>>>(events, features, offsets, n, nb);
    // 2) conv on fp16 tensor cores (normalization fused into halo staging)
    {
        dim3 grid((WW + TLX - 1) / TLX, HH / TLY, BB);   // 10 x 15 x 8
        conv_hmma_kernel<<<grid, CONV_THREADS, DYN_BYTES>>>(weight);
    }
    // 3) gather + bias (2 events per thread, MLP=4)
    {
        int threads_total = ((n + 1) / 2) * 4;
        gather_kernel<<<(threads_total + T - 1) / T, T>>>(bias, (float*)d_out, n);
    }
}